// round 3
// baseline (speedup 1.0000x reference)
#include <cuda_runtime.h>
#include <cuda_fp16.h>
#include <math.h>
#include <stdint.h>

#define BSZ 64
#define SSZ 512
#define DSZ 1024
#define HSZ 1024
#define OFF_HN 33554432              // B*S*H
#define OFF_CN (33554432 + 65536)    // + B*H
#define NCTA 128

// ---------------- static device scratch (allocations are forbidden) --------
__device__ float  g_xp[(size_t)SSZ * BSZ * 4096];   // x_proj [t][b][4H], biases folded
__device__ __half g_xh[(size_t)BSZ * SSZ * DSZ];    // inputs fp16
__device__ __half g_wh[(size_t)4096 * DSZ];         // W_ih fp16
__device__ __half g_h[2][BSZ * HSZ];                // ping-pong hidden state fp16
__device__ int    g_cnt[SSZ];                       // per-step arrival counters

// ---------------- helpers ---------------------------------------------------
__device__ __forceinline__ unsigned h2u(__half2 v) {
    return *reinterpret_cast<unsigned*>(&v);
}
__device__ __forceinline__ float fsigmoid(float x) {
    return 1.0f / (1.0f + __expf(-x));
}
__device__ __forceinline__ float ftanh(float x) {
    return 2.0f / (1.0f + __expf(-2.0f * x)) - 1.0f;
}

#define MMA16816(c, a, b)                                                     \
    asm volatile(                                                             \
        "mma.sync.aligned.m16n8k16.row.col.f32.f16.f16.f32 "                  \
        "{%0,%1,%2,%3},{%4,%5,%6,%7},{%8,%9},{%0,%1,%2,%3};"                  \
        : "+f"((c)[0]), "+f"((c)[1]), "+f"((c)[2]), "+f"((c)[3])              \
        : "r"((a)[0]), "r"((a)[1]), "r"((a)[2]), "r"((a)[3]),                 \
          "r"((b)[0]), "r"((b)[1]))

// ---------------- phase 0: conversions + state init -------------------------
__global__ void prep_kernel(const float* __restrict__ inp,
                            const float* __restrict__ h0,
                            const float* __restrict__ wih) {
    size_t i = (size_t)blockIdx.x * blockDim.x + threadIdx.x;
    if (i < (size_t)BSZ * SSZ * DSZ) g_xh[i] = __float2half(inp[i]);
    if (i < (size_t)4096 * DSZ)      g_wh[i] = __float2half(wih[i]);
    if (i < BSZ * HSZ)               g_h[0][i] = __float2half(h0[i]);
    if (i < SSZ)                     g_cnt[i] = 0;
}

// ---------------- phase 1: x_proj = x @ Wih^T + bi + bh ---------------------
// M=32768 (b*512+s), N=4096, K=1024. CTA tile 128x128, 4 warps of 64x64.
__global__ __launch_bounds__(128) void xproj_kernel(
    const float* __restrict__ bi, const float* __restrict__ bh) {
    __shared__ __half As[128 * 40];
    __shared__ __half Bs[128 * 40];

    const int m0 = blockIdx.y * 128;
    const int n0 = blockIdx.x * 128;
    const int tid = threadIdx.x;
    const int warp = tid >> 5, lane = tid & 31;
    const int gid = lane >> 2, tig = lane & 3;
    const int rb = (warp & 1) * 64, cb = (warp >> 1) * 64;

    float acc[4][8][4];
#pragma unroll
    for (int m = 0; m < 4; m++)
#pragma unroll
        for (int n = 0; n < 8; n++)
#pragma unroll
            for (int r = 0; r < 4; r++) acc[m][n][r] = 0.0f;

    for (int kb = 0; kb < 1024; kb += 32) {
#pragma unroll
        for (int i = 0; i < 4; i++) {
            int j = tid + i * 128;          // 0..511
            int row = j >> 2, q = j & 3;    // row 0..127, 16B chunk 0..3
            *(int4*)&As[row * 40 + q * 8] =
                *(const int4*)&g_xh[(size_t)(m0 + row) * 1024 + kb + q * 8];
            *(int4*)&Bs[row * 40 + q * 8] =
                *(const int4*)&g_wh[(size_t)(n0 + row) * 1024 + kb + q * 8];
        }
        __syncthreads();
#pragma unroll
        for (int ks = 0; ks < 32; ks += 16) {
            unsigned a[4][4], b[8][2];
#pragma unroll
            for (int m = 0; m < 4; m++) {
                int ra = rb + m * 16 + gid;
                a[m][0] = *(const unsigned*)&As[ra * 40 + ks + 2 * tig];
                a[m][1] = *(const unsigned*)&As[(ra + 8) * 40 + ks + 2 * tig];
                a[m][2] = *(const unsigned*)&As[ra * 40 + ks + 8 + 2 * tig];
                a[m][3] = *(const unsigned*)&As[(ra + 8) * 40 + ks + 8 + 2 * tig];
            }
#pragma unroll
            for (int n = 0; n < 8; n++) {
                int nc = cb + n * 8 + gid;
                b[n][0] = *(const unsigned*)&Bs[nc * 40 + ks + 2 * tig];
                b[n][1] = *(const unsigned*)&Bs[nc * 40 + ks + 8 + 2 * tig];
            }
#pragma unroll
            for (int m = 0; m < 4; m++)
#pragma unroll
                for (int n = 0; n < 8; n++) MMA16816(acc[m][n], a[m], b[n]);
        }
        __syncthreads();
    }

    // epilogue: + (bias_ih + bias_hh), scatter rows to [s][b][n]
#pragma unroll
    for (int m = 0; m < 4; m++) {
#pragma unroll
        for (int n = 0; n < 8; n++) {
            int row = m0 + rb + m * 16 + gid;
            int col = n0 + cb + n * 8 + 2 * tig;
            float2 b1 = *(const float2*)&bi[col];
            float2 b2 = *(const float2*)&bh[col];
            float bs0 = b1.x + b2.x, bs1 = b1.y + b2.y;
            {
                int s = row & 511, bb = row >> 9;
                float2 v = make_float2(acc[m][n][0] + bs0, acc[m][n][1] + bs1);
                *(float2*)&g_xp[(size_t)((s << 6) + bb) * 4096 + col] = v;
            }
            {
                int r2 = row + 8;
                int s = r2 & 511, bb = r2 >> 9;
                float2 v = make_float2(acc[m][n][2] + bs0, acc[m][n][3] + bs1);
                *(float2*)&g_xp[(size_t)((s << 6) + bb) * 4096 + col] = v;
            }
        }
    }
}

// ---------------- phase 2: persistent recurrence ----------------------------
// 128 CTAs x 256 threads. CTA c owns h-cols [8c, 8c+8) -> 32 gate columns.
// 8 warps K-split (128 K each); W_hh fragments resident in registers.
__global__ __launch_bounds__(256) void lstm_rec_kernel(
    const float* __restrict__ c0, const float* __restrict__ Whh,
    float* __restrict__ out) {
    __shared__ float gbuf[4][64][34];

    const int cta = blockIdx.x;
    const int tid = threadIdx.x;
    const int warp = tid >> 5, lane = tid & 31;
    const int gid = lane >> 2, tig = lane & 3;
    const int K0 = warp * 128;
    const int hcb = cta * 8;

    // --- load W_hh fragments into registers (once) ---
    unsigned Breg[4][8][2];
#pragma unroll
    for (int g = 0; g < 4; g++) {
        const float* wr = Whh + (size_t)(g * 1024 + hcb + gid) * 1024 + K0;
#pragma unroll
        for (int s = 0; s < 8; s++) {
            int k = s * 16 + 2 * tig;
            Breg[g][s][0] = h2u(__floats2half2_rn(wr[k], wr[k + 1]));
            Breg[g][s][1] = h2u(__floats2half2_rn(wr[k + 8], wr[k + 9]));
        }
    }

    // --- elementwise ownership: rows er, cols (hcb+ec, hcb+ec+1) ---
    const int er = tid >> 2;
    const int ec = (tid & 3) * 2;
    float cst[2];
    cst[0] = c0[er * 1024 + hcb + ec];
    cst[1] = c0[er * 1024 + hcb + ec + 1];

#pragma unroll 1
    for (int t = 0; t < SSZ; t++) {
        const __half* hb = g_h[t & 1];

        float acc[4][4][4];
#pragma unroll
        for (int m = 0; m < 4; m++)
#pragma unroll
            for (int g = 0; g < 4; g++)
#pragma unroll
                for (int r = 0; r < 4; r++) acc[m][g][r] = 0.0f;

#pragma unroll
        for (int s = 0; s < 8; s++) {
            const int k = K0 + s * 16 + 2 * tig;
            unsigned a[4][4];
#pragma unroll
            for (int m = 0; m < 4; m++) {
                const __half* hr = hb + (m * 16 + gid) * 1024 + k;
                a[m][0] = __ldcg((const unsigned*)hr);
                a[m][1] = __ldcg((const unsigned*)(hr + 8 * 1024));
                a[m][2] = __ldcg((const unsigned*)(hr + 8));
                a[m][3] = __ldcg((const unsigned*)(hr + 8 * 1024 + 8));
            }
#pragma unroll
            for (int m = 0; m < 4; m++)
#pragma unroll
                for (int g = 0; g < 4; g++) MMA16816(acc[m][g], a[m], Breg[g][s]);
        }

        // --- cross-warp K reduction via smem (two-phase into gbuf[0..3]) ---
        if (warp < 4) {
#pragma unroll
            for (int m = 0; m < 4; m++)
#pragma unroll
                for (int g = 0; g < 4; g++) {
                    int r0 = m * 16 + gid, n = g * 8 + 2 * tig;
                    *(float2*)&gbuf[warp][r0][n] =
                        make_float2(acc[m][g][0], acc[m][g][1]);
                    *(float2*)&gbuf[warp][r0 + 8][n] =
                        make_float2(acc[m][g][2], acc[m][g][3]);
                }
        }
        __syncthreads();
        if (warp >= 4) {
            int w4 = warp - 4;
#pragma unroll
            for (int m = 0; m < 4; m++)
#pragma unroll
                for (int g = 0; g < 4; g++) {
                    int r0 = m * 16 + gid, n = g * 8 + 2 * tig;
                    float2* p0 = (float2*)&gbuf[w4][r0][n];
                    float2 v0 = *p0;
                    v0.x += acc[m][g][0]; v0.y += acc[m][g][1];
                    *p0 = v0;
                    float2* p1 = (float2*)&gbuf[w4][r0 + 8][n];
                    float2 v1 = *p1;
                    v1.x += acc[m][g][2]; v1.y += acc[m][g][3];
                    *p1 = v1;
                }
        }
        __syncthreads();

        // --- elementwise LSTM cell for (er, ec), (er, ec+1) ---
        const float* xp = g_xp + ((size_t)t * 64 + er) * 4096 + hcb + ec;
        float2 gate2[4];
#pragma unroll
        for (int g = 0; g < 4; g++) {
            float2 v = *(const float2*)(xp + g * 1024);
#pragma unroll
            for (int w4 = 0; w4 < 4; w4++) {
                float2 pv = *(const float2*)&gbuf[w4][er][g * 8 + ec];
                v.x += pv.x; v.y += pv.y;
            }
            gate2[g] = v;
        }

        float hres[2];
#pragma unroll
        for (int j = 0; j < 2; j++) {
            float gi = j ? gate2[0].y : gate2[0].x;
            float gf = j ? gate2[1].y : gate2[1].x;
            float gg = j ? gate2[2].y : gate2[2].x;
            float go = j ? gate2[3].y : gate2[3].x;
            float i_ = fsigmoid(gi);
            float f_ = fsigmoid(gf);
            float g_ = ftanh(gg);
            float o_ = fsigmoid(go);
            float cn = f_ * cst[j] + i_ * g_;
            cst[j] = cn;
            hres[j] = o_ * ftanh(cn);
        }

        // outputs[b][t][h]
        *(float2*)&out[((size_t)er * 512 + t) * 1024 + hcb + ec] =
            make_float2(hres[0], hres[1]);
        // next-step h (fp16)
        *(__half2*)&g_h[(t + 1) & 1][er * 1024 + hcb + ec] =
            __floats2half2_rn(hres[0], hres[1]);

        if (t == SSZ - 1) {
            *(float2*)&out[OFF_HN + er * 1024 + hcb + ec] =
                make_float2(hres[0], hres[1]);
            *(float2*)&out[OFF_CN + er * 1024 + hcb + ec] =
                make_float2(cst[0], cst[1]);
        }

        // --- global step barrier ---
        if (t < SSZ - 1) {
            __syncthreads();           // all h stores issued before arrival
            if (tid == 0) {
                __threadfence();
                atomicAdd(&g_cnt[t], 1);
                while (((volatile int*)g_cnt)[t] < NCTA) { }
                __threadfence();
            }
            __syncthreads();
        }
    }
}

// ---------------- launch -----------------------------------------------------
extern "C" void kernel_launch(void* const* d_in, const int* in_sizes, int n_in,
                              void* d_out, int out_size) {
    const float* inp = (const float*)d_in[0];
    const float* h0  = (const float*)d_in[1];
    const float* c0  = (const float*)d_in[2];
    const float* wih = (const float*)d_in[3];
    const float* whh = (const float*)d_in[4];
    const float* bih = (const float*)d_in[5];
    const float* bhh = (const float*)d_in[6];
    float* out = (float*)d_out;

    prep_kernel<<<131072, 256>>>(inp, h0, wih);
    dim3 g1(32, 256);
    xproj_kernel<<<g1, 128>>>(bih, bhh);
    lstm_rec_kernel<<<NCTA, 256>>>(c0, whh, out);
}

// round 4
// speedup vs baseline: 1.3369x; 1.3369x over previous
#include <cuda_runtime.h>
#include <cuda_fp16.h>
#include <math.h>
#include <stdint.h>

#define BSZ 64
#define SSZ 512
#define DSZ 1024
#define HSZ 1024
#define OFF_HN 33554432              // B*S*H
#define OFF_CN (33554432 + 65536)    // + B*H
#define NCTA 128
#define HPAD 1040                    // h smem row stride (halves): 16B shift/row

// ---------------- static device scratch (allocations are forbidden) --------
__device__ float  g_xp[(size_t)SSZ * BSZ * 4096];   // x_proj [t][b][4H], biases folded
__device__ __half g_xh[(size_t)BSZ * SSZ * DSZ];    // inputs fp16
__device__ __half g_wh[(size_t)4096 * DSZ];         // W_ih fp16
__device__ __half g_h[2][BSZ * HSZ];                // ping-pong hidden state fp16
__device__ int    g_cnt[SSZ];                       // per-step arrival counters

// ---------------- helpers ---------------------------------------------------
__device__ __forceinline__ unsigned h2u(__half2 v) {
    return *reinterpret_cast<unsigned*>(&v);
}
__device__ __forceinline__ float fsigmoid(float x) {
    return 1.0f / (1.0f + __expf(-x));
}
__device__ __forceinline__ float ftanh(float x) {
    return 2.0f / (1.0f + __expf(-2.0f * x)) - 1.0f;
}

#define MMA16816(c, a, b)                                                     \
    asm volatile(                                                             \
        "mma.sync.aligned.m16n8k16.row.col.f32.f16.f16.f32 "                  \
        "{%0,%1,%2,%3},{%4,%5,%6,%7},{%8,%9},{%0,%1,%2,%3};"                  \
        : "+f"((c)[0]), "+f"((c)[1]), "+f"((c)[2]), "+f"((c)[3])              \
        : "r"((a)[0]), "r"((a)[1]), "r"((a)[2]), "r"((a)[3]),                 \
          "r"((b)[0]), "r"((b)[1]))

#define CP_ASYNC16(dst, src)                                                  \
    asm volatile("cp.async.cg.shared.global [%0], [%1], 16;" ::               \
                 "r"(dst), "l"(src))
#define CP_COMMIT  asm volatile("cp.async.commit_group;")
#define CP_WAIT0   asm volatile("cp.async.wait_group 0;")

#define LDSM_X4(r0, r1, r2, r3, addr)                                         \
    asm volatile("ldmatrix.sync.aligned.m8n8.x4.shared.b16 "                  \
                 "{%0,%1,%2,%3}, [%4];"                                       \
                 : "=r"(r0), "=r"(r1), "=r"(r2), "=r"(r3) : "r"(addr))

// ---------------- phase 0: conversions + state init -------------------------
__global__ void prep_kernel(const float* __restrict__ inp,
                            const float* __restrict__ h0,
                            const float* __restrict__ wih) {
    size_t i = (size_t)blockIdx.x * blockDim.x + threadIdx.x;
    if (i < (size_t)BSZ * SSZ * DSZ) g_xh[i] = __float2half(inp[i]);
    if (i < (size_t)4096 * DSZ)      g_wh[i] = __float2half(wih[i]);
    if (i < BSZ * HSZ)               g_h[0][i] = __float2half(h0[i]);
    if (i < SSZ)                     g_cnt[i] = 0;
}

// ---------------- phase 1: x_proj = x @ Wih^T + bi + bh ---------------------
// M=32768 (b*512+s), N=4096, K=1024. CTA tile 128x128, 4 warps of 64x64.
__global__ __launch_bounds__(128) void xproj_kernel(
    const float* __restrict__ bi, const float* __restrict__ bh) {
    __shared__ __half As[128 * 40];
    __shared__ __half Bs[128 * 40];

    const int m0 = blockIdx.y * 128;
    const int n0 = blockIdx.x * 128;
    const int tid = threadIdx.x;
    const int warp = tid >> 5, lane = tid & 31;
    const int gid = lane >> 2, tig = lane & 3;
    const int rb = (warp & 1) * 64, cb = (warp >> 1) * 64;

    float acc[4][8][4];
#pragma unroll
    for (int m = 0; m < 4; m++)
#pragma unroll
        for (int n = 0; n < 8; n++)
#pragma unroll
            for (int r = 0; r < 4; r++) acc[m][n][r] = 0.0f;

    for (int kb = 0; kb < 1024; kb += 32) {
#pragma unroll
        for (int i = 0; i < 4; i++) {
            int j = tid + i * 128;
            int row = j >> 2, q = j & 3;
            *(int4*)&As[row * 40 + q * 8] =
                *(const int4*)&g_xh[(size_t)(m0 + row) * 1024 + kb + q * 8];
            *(int4*)&Bs[row * 40 + q * 8] =
                *(const int4*)&g_wh[(size_t)(n0 + row) * 1024 + kb + q * 8];
        }
        __syncthreads();
#pragma unroll
        for (int ks = 0; ks < 32; ks += 16) {
            unsigned a[4][4], b[8][2];
#pragma unroll
            for (int m = 0; m < 4; m++) {
                int ra = rb + m * 16 + gid;
                a[m][0] = *(const unsigned*)&As[ra * 40 + ks + 2 * tig];
                a[m][1] = *(const unsigned*)&As[(ra + 8) * 40 + ks + 2 * tig];
                a[m][2] = *(const unsigned*)&As[ra * 40 + ks + 8 + 2 * tig];
                a[m][3] = *(const unsigned*)&As[(ra + 8) * 40 + ks + 8 + 2 * tig];
            }
#pragma unroll
            for (int n = 0; n < 8; n++) {
                int nc = cb + n * 8 + gid;
                b[n][0] = *(const unsigned*)&Bs[nc * 40 + ks + 2 * tig];
                b[n][1] = *(const unsigned*)&Bs[nc * 40 + ks + 8 + 2 * tig];
            }
#pragma unroll
            for (int m = 0; m < 4; m++)
#pragma unroll
                for (int n = 0; n < 8; n++) MMA16816(acc[m][n], a[m], b[n]);
        }
        __syncthreads();
    }

#pragma unroll
    for (int m = 0; m < 4; m++) {
#pragma unroll
        for (int n = 0; n < 8; n++) {
            int row = m0 + rb + m * 16 + gid;
            int col = n0 + cb + n * 8 + 2 * tig;
            float2 b1 = *(const float2*)&bi[col];
            float2 b2 = *(const float2*)&bh[col];
            float bs0 = b1.x + b2.x, bs1 = b1.y + b2.y;
            {
                int s = row & 511, bb = row >> 9;
                float2 v = make_float2(acc[m][n][0] + bs0, acc[m][n][1] + bs1);
                *(float2*)&g_xp[(size_t)((s << 6) + bb) * 4096 + col] = v;
            }
            {
                int r2 = row + 8;
                int s = r2 & 511, bb = r2 >> 9;
                float2 v = make_float2(acc[m][n][2] + bs0, acc[m][n][3] + bs1);
                *(float2*)&g_xp[(size_t)((s << 6) + bb) * 4096 + col] = v;
            }
        }
    }
}

// ---------------- phase 2: persistent recurrence ----------------------------
// 128 CTAs x 256 threads. CTA c owns h-cols [8c, 8c+8) -> 32 gate columns.
// 8 warps K-split (128 K each); W_hh fragments resident in registers.
// h staged per step: coalesced cp.async into padded smem, ldmatrix A-frags.
__global__ __launch_bounds__(256) void lstm_rec_kernel(
    const float* __restrict__ c0, const float* __restrict__ Whh,
    float* __restrict__ out) {
    extern __shared__ __half sm[];
    __half* Hs = sm;                         // [64][HPAD] halves = 133120 B
    float* gb = (float*)(sm + 64 * HPAD);    // [4][64][34] floats = 34816 B
    const unsigned hs_base = (unsigned)__cvta_generic_to_shared(Hs);

    const int cta = blockIdx.x;
    const int tid = threadIdx.x;
    const int warp = tid >> 5, lane = tid & 31;
    const int gid = lane >> 2, tig = lane & 3;
    const int K0 = warp * 128;
    const int hcb = cta * 8;

    // ldmatrix per-lane source address pieces
    const int lrow = lane & 15;              // row within m16 tile
    const int lkhi = (lane >> 4) * 8;        // k offset 0 or 8

    // --- load W_hh fragments into registers (once) ---
    unsigned Breg[4][8][2];
#pragma unroll
    for (int g = 0; g < 4; g++) {
        const float* wr = Whh + (size_t)(g * 1024 + hcb + gid) * 1024 + K0;
#pragma unroll
        for (int s = 0; s < 8; s++) {
            int k = s * 16 + 2 * tig;
            Breg[g][s][0] = h2u(__floats2half2_rn(wr[k], wr[k + 1]));
            Breg[g][s][1] = h2u(__floats2half2_rn(wr[k + 8], wr[k + 9]));
        }
    }

    // --- elementwise ownership: row er, cols (hcb+ec, hcb+ec+1) ---
    const int er = tid >> 2;
    const int ec = (tid & 3) * 2;
    float cst[2];
    cst[0] = c0[er * 1024 + hcb + ec];
    cst[1] = c0[er * 1024 + hcb + ec + 1];

#pragma unroll 1
    for (int t = 0; t < SSZ; t++) {
        const __half* hb = g_h[t & 1];

        // prefetch x_proj gates (independent of h)
        const float* xp = g_xp + ((size_t)t * 64 + er) * 4096 + hcb + ec;
        float2 xg[4];
#pragma unroll
        for (int g = 0; g < 4; g++) xg[g] = *(const float2*)(xp + g * 1024);

        // --- stage h into smem: 8192 16B chunks, coalesced ---
#pragma unroll
        for (int j = 0; j < 32; j++) {
            int chunk = tid + j * 256;
            int row = chunk >> 7;
            int c8 = (chunk & 127) << 3;
            CP_ASYNC16(hs_base + (unsigned)(row * HPAD + c8) * 2,
                       hb + row * 1024 + c8);
        }
        CP_COMMIT;
        CP_WAIT0;
        __syncthreads();

        // --- MMA: 4 m-tiles x 4 gates, K-split across warps ---
        float acc[4][4][4];
#pragma unroll
        for (int m = 0; m < 4; m++)
#pragma unroll
            for (int g = 0; g < 4; g++)
#pragma unroll
                for (int r = 0; r < 4; r++) acc[m][g][r] = 0.0f;

#pragma unroll
        for (int s = 0; s < 8; s++) {
            unsigned a[4][4];
#pragma unroll
            for (int m = 0; m < 4; m++) {
                unsigned addr = hs_base +
                    (unsigned)((m * 16 + lrow) * HPAD + K0 + s * 16 + lkhi) * 2;
                LDSM_X4(a[m][0], a[m][1], a[m][2], a[m][3], addr);
            }
#pragma unroll
            for (int m = 0; m < 4; m++)
#pragma unroll
                for (int g = 0; g < 4; g++) MMA16816(acc[m][g], a[m], Breg[g][s]);
        }

        // --- cross-warp K reduction via smem (two-phase) ---
        if (warp < 4) {
#pragma unroll
            for (int m = 0; m < 4; m++)
#pragma unroll
                for (int g = 0; g < 4; g++) {
                    int r0 = m * 16 + gid, n = g * 8 + 2 * tig;
                    *(float2*)&gb[((warp * 64 + r0) * 34 + n)] =
                        make_float2(acc[m][g][0], acc[m][g][1]);
                    *(float2*)&gb[((warp * 64 + r0 + 8) * 34 + n)] =
                        make_float2(acc[m][g][2], acc[m][g][3]);
                }
        }
        __syncthreads();
        if (warp >= 4) {
            int w4 = warp - 4;
#pragma unroll
            for (int m = 0; m < 4; m++)
#pragma unroll
                for (int g = 0; g < 4; g++) {
                    int r0 = m * 16 + gid, n = g * 8 + 2 * tig;
                    float2* p0 = (float2*)&gb[((w4 * 64 + r0) * 34 + n)];
                    float2 v0 = *p0;
                    v0.x += acc[m][g][0]; v0.y += acc[m][g][1];
                    *p0 = v0;
                    float2* p1 = (float2*)&gb[((w4 * 64 + r0 + 8) * 34 + n)];
                    float2 v1 = *p1;
                    v1.x += acc[m][g][2]; v1.y += acc[m][g][3];
                    *p1 = v1;
                }
        }
        __syncthreads();

        // --- elementwise LSTM cell for (er, ec), (er, ec+1) ---
        float2 gate2[4];
#pragma unroll
        for (int g = 0; g < 4; g++) {
            float2 v = xg[g];
#pragma unroll
            for (int w4 = 0; w4 < 4; w4++) {
                float2 pv = *(const float2*)&gb[((w4 * 64 + er) * 34 + g * 8 + ec)];
                v.x += pv.x; v.y += pv.y;
            }
            gate2[g] = v;
        }

        float hres[2];
#pragma unroll
        for (int j = 0; j < 2; j++) {
            float gi = j ? gate2[0].y : gate2[0].x;
            float gf = j ? gate2[1].y : gate2[1].x;
            float gg = j ? gate2[2].y : gate2[2].x;
            float go = j ? gate2[3].y : gate2[3].x;
            float i_ = fsigmoid(gi);
            float f_ = fsigmoid(gf);
            float g_ = ftanh(gg);
            float o_ = fsigmoid(go);
            float cn = f_ * cst[j] + i_ * g_;
            cst[j] = cn;
            hres[j] = o_ * ftanh(cn);
        }

        // outputs[b][t][h]
        *(float2*)&out[((size_t)er * 512 + t) * 1024 + hcb + ec] =
            make_float2(hres[0], hres[1]);
        // next-step h (fp16)
        *(__half2*)&g_h[(t + 1) & 1][er * 1024 + hcb + ec] =
            __floats2half2_rn(hres[0], hres[1]);

        if (t == SSZ - 1) {
            *(float2*)&out[OFF_HN + er * 1024 + hcb + ec] =
                make_float2(hres[0], hres[1]);
            *(float2*)&out[OFF_CN + er * 1024 + hcb + ec] =
                make_float2(cst[0], cst[1]);
        }

        // --- global step barrier (release/acquire) ---
        if (t < SSZ - 1) {
            __syncthreads();
            if (tid == 0) {
                int v;
                asm volatile("atom.global.add.release.gpu.s32 %0, [%1], 1;"
                             : "=r"(v) : "l"(&g_cnt[t]) : "memory");
                v += 1;
                while (v < NCTA) {
                    asm volatile("ld.global.acquire.gpu.s32 %0, [%1];"
                                 : "=r"(v) : "l"(&g_cnt[t]) : "memory");
                }
            }
            __syncthreads();
        }
    }
}

// ---------------- launch -----------------------------------------------------
extern "C" void kernel_launch(void* const* d_in, const int* in_sizes, int n_in,
                              void* d_out, int out_size) {
    const float* inp = (const float*)d_in[0];
    const float* h0  = (const float*)d_in[1];
    const float* c0  = (const float*)d_in[2];
    const float* wih = (const float*)d_in[3];
    const float* whh = (const float*)d_in[4];
    const float* bih = (const float*)d_in[5];
    const float* bhh = (const float*)d_in[6];
    float* out = (float*)d_out;

    const int rec_smem = 64 * HPAD * 2 + 4 * 64 * 34 * 4;  // 167936 B
    static int attr_done = 0;
    if (!attr_done) {
        cudaFuncSetAttribute(lstm_rec_kernel,
                             cudaFuncAttributeMaxDynamicSharedMemorySize,
                             rec_smem);
        attr_done = 1;
    }

    prep_kernel<<<131072, 256>>>(inp, h0, wih);
    dim3 g1(32, 256);
    xproj_kernel<<<g1, 128>>>(bih, bhh);
    lstm_rec_kernel<<<NCTA, 256, rec_smem>>>(c0, whh, out);
}